// round 2
// baseline (speedup 1.0000x reference)
#include <cuda_runtime.h>
#include <cuda_bf16.h>
#include <math.h>

// Problem constants (constexpr, NOT macros — avoids identifier collisions)
constexpr int cB   = 128;
constexpr int cT   = 256;
constexpr int cC   = 384;
constexpr int cH   = 6;
constexpr int cHS  = 64;
constexpr int cDFF = 1536;
constexpr int cBT  = cB * cT;          // 32768

// ---------------- scratch (static device globals; no allocation) -------------
__device__ float g_h   [cBT * cC];          // LN output (reused for LN1 and LN2)
__device__ float g_q   [cB * cH * cT * cHS];
__device__ float g_k   [cB * cH * cT * cHS];
__device__ float g_v   [cB * cH * cT * cHS];
__device__ float g_attn[cBT * cC];          // attention output, (B,T,H*HS) layout
__device__ float g_x1  [cBT * cC];          // x + self-attention (residual 1)
__device__ float g_ff1 [cBT * cDFF];        // relu(h2 @ W1 + b1)

// ---------------- LayerNorm: one block (128 thr) per row ---------------------
__global__ void ln_kernel(const float* __restrict__ x,
                          const float* __restrict__ g,
                          const float* __restrict__ b,
                          float* __restrict__ out)
{
    int row = blockIdx.x;
    const float* xr = x + (size_t)row * cC;
    float* orow     = out + (size_t)row * cC;
    int t = threadIdx.x;                // 0..127

    float v0 = xr[t], v1 = xr[t + 128], v2 = xr[t + 256];
    float s  = v0 + v1 + v2;

    __shared__ float sh[4];
    __shared__ float sh2[4];
    #pragma unroll
    for (int o = 16; o; o >>= 1) s += __shfl_xor_sync(0xffffffffu, s, o);
    if ((t & 31) == 0) sh[t >> 5] = s;
    __syncthreads();
    float mu = (sh[0] + sh[1] + sh[2] + sh[3]) * (1.0f / cC);

    float d0 = v0 - mu, d1 = v1 - mu, d2 = v2 - mu;
    float sq = d0 * d0 + d1 * d1 + d2 * d2;
    #pragma unroll
    for (int o = 16; o; o >>= 1) sq += __shfl_xor_sync(0xffffffffu, sq, o);
    if ((t & 31) == 0) sh2[t >> 5] = sq;
    __syncthreads();
    float var = (sh2[0] + sh2[1] + sh2[2] + sh2[3]) * (1.0f / cC);
    float r = rsqrtf(var + 1e-5f);

    orow[t]       = d0 * r * g[t]       + b[t];
    orow[t + 128] = d1 * r * g[t + 128] + b[t + 128];
    orow[t + 256] = d2 * r * g[t + 256] + b[t + 256];
}

// ---------------- QKV projection: 64x64x16 tile SGEMM, batched over z --------
// z = (b*H + head)*3 + which.  A = h[b] (T x C), W = W{q,k,v}[head] (C x HS).
__global__ __launch_bounds__(256) void qkv_kernel(
    const float* __restrict__ hbuf,
    const float* __restrict__ Wq,
    const float* __restrict__ Wk,
    const float* __restrict__ Wv)
{
    int z = blockIdx.z;
    int which = z % 3;
    int bh = z / 3;
    int bidx = bh / cH;
    int head = bh % cH;

    const float* W = (which == 0 ? Wq : (which == 1 ? Wk : Wv)) + (size_t)head * cC * cHS;
    float* Out = (which == 0 ? g_q : (which == 1 ? g_k : g_v)) + (size_t)bh * cT * cHS;
    const float* A = hbuf + (size_t)bidx * cT * cC;

    int m0 = blockIdx.y * 64;

    __shared__ float As[16][68];   // transposed A tile, padded
    __shared__ float Bs[16][64];

    int tid  = threadIdx.x;
    int rowA = tid >> 2;           // 0..63
    int colA = (tid & 3) * 4;      // 0,4,8,12
    int rowB = tid >> 4;           // 0..15
    int colB = (tid & 15) * 4;     // 0..60
    int tx = tid & 15, ty = tid >> 4;

    float acc[4][4] = {};

    for (int k0 = 0; k0 < cC; k0 += 16) {
        float4 a4 = *(const float4*)(A + (size_t)(m0 + rowA) * cC + k0 + colA);
        As[colA + 0][rowA] = a4.x;
        As[colA + 1][rowA] = a4.y;
        As[colA + 2][rowA] = a4.z;
        As[colA + 3][rowA] = a4.w;
        float4 b4 = *(const float4*)(W + (size_t)(k0 + rowB) * cHS + colB);
        *(float4*)&Bs[rowB][colB] = b4;
        __syncthreads();
        #pragma unroll
        for (int k = 0; k < 16; k++) {
            float4 ra = *(const float4*)&As[k][ty * 4];
            float4 rb = *(const float4*)&Bs[k][tx * 4];
            float av[4] = {ra.x, ra.y, ra.z, ra.w};
            float bv[4] = {rb.x, rb.y, rb.z, rb.w};
            #pragma unroll
            for (int i = 0; i < 4; i++)
                #pragma unroll
                for (int j = 0; j < 4; j++)
                    acc[i][j] += av[i] * bv[j];
        }
        __syncthreads();
    }

    #pragma unroll
    for (int i = 0; i < 4; i++) {
        float4 v;
        v.x = acc[i][0]; v.y = acc[i][1]; v.z = acc[i][2]; v.w = acc[i][3];
        *(float4*)(Out + (size_t)(m0 + ty * 4 + i) * cHS + tx * 4) = v;
    }
}

// ---------------- causal attention: one warp per query row -------------------
__global__ void attn_kernel(float* __restrict__ out)
{
    int warp = (blockIdx.x * blockDim.x + threadIdx.x) >> 5;
    int lane = threadIdx.x & 31;
    int t  = warp % cT;
    int bh = warp / cT;            // b*H + head

    const float* qr = g_q + ((size_t)bh * cT + t) * cHS;
    const float* kb = g_k + (size_t)bh * cT * cHS;
    const float* vb = g_v + (size_t)bh * cT * cHS;

    float q0 = qr[lane], q1 = qr[lane + 32];

    float m = -1e30f, l = 0.0f, a0 = 0.0f, a1 = 0.0f;
    const float scale = 0.125f;    // 1/sqrt(64)

    for (int s = 0; s <= t; s++) {
        const float* kr = kb + (size_t)s * cHS;
        float p = q0 * kr[lane] + q1 * kr[lane + 32];
        #pragma unroll
        for (int o = 16; o; o >>= 1) p += __shfl_xor_sync(0xffffffffu, p, o);
        p *= scale;
        float nm = fmaxf(m, p);
        float corr = __expf(m - nm);
        float e = __expf(p - nm);
        const float* vr = vb + (size_t)s * cHS;
        a0 = a0 * corr + e * vr[lane];
        a1 = a1 * corr + e * vr[lane + 32];
        l = l * corr + e;
        m = nm;
    }

    int bidx = bh / cH;
    int head = bh % cH;
    float inv = 1.0f / l;
    size_t base = ((size_t)(bidx * cT + t)) * cC + head * cHS;
    out[base + lane]      = a0 * inv;
    out[base + lane + 32] = a1 * inv;
}

// ---------------- generic 128x128x8 SGEMM with fused epilogue ----------------
// A: M x K (row-major, lda=K), B: K x N (row-major, ldb=N), C: M x N (ldc=N)
// val = acc + bias[n]; if relu val = max(val,0); if resid val += resid[m*N+n]
__global__ __launch_bounds__(256) void sgemm128(
    const float* __restrict__ A, const float* __restrict__ Bw,
    const float* __restrict__ bias, const float* __restrict__ resid,
    float* __restrict__ Cout,
    int M, int N, int K, int relu)
{
    __shared__ float As[8][132];
    __shared__ float Bs[8][128];

    int tid = threadIdx.x;
    int bx = blockIdx.x;           // N tile
    int by = blockIdx.y;           // M tile

    const float* Abase = A + (size_t)by * 128 * K;
    const float* Bbase = Bw + bx * 128;

    int rowA = tid >> 1;           // 0..127
    int colA = (tid & 1) * 4;      // 0 or 4
    int rowB = tid >> 5;           // 0..7
    int colB = (tid & 31) * 4;     // 0..124
    int tx = tid & 15, ty = tid >> 4;

    float acc[8][8] = {};

    for (int k0 = 0; k0 < K; k0 += 8) {
        float4 a4 = *(const float4*)(Abase + (size_t)rowA * K + k0 + colA);
        As[colA + 0][rowA] = a4.x;
        As[colA + 1][rowA] = a4.y;
        As[colA + 2][rowA] = a4.z;
        As[colA + 3][rowA] = a4.w;
        float4 b4 = *(const float4*)(Bbase + (size_t)(k0 + rowB) * N + colB);
        *(float4*)&Bs[rowB][colB] = b4;
        __syncthreads();
        #pragma unroll
        for (int k = 0; k < 8; k++) {
            float ra[8], rb[8];
            *(float4*)ra       = *(const float4*)&As[k][ty * 8];
            *(float4*)(ra + 4) = *(const float4*)&As[k][ty * 8 + 4];
            *(float4*)rb       = *(const float4*)&Bs[k][tx * 8];
            *(float4*)(rb + 4) = *(const float4*)&Bs[k][tx * 8 + 4];
            #pragma unroll
            for (int i = 0; i < 8; i++)
                #pragma unroll
                for (int j = 0; j < 8; j++)
                    acc[i][j] += ra[i] * rb[j];
        }
        __syncthreads();
    }

    int crow0 = by * 128 + ty * 8;
    int ccol0 = bx * 128 + tx * 8;
    #pragma unroll
    for (int i = 0; i < 8; i++) {
        size_t base = (size_t)(crow0 + i) * N + ccol0;
        #pragma unroll
        for (int j = 0; j < 8; j += 4) {
            float4 v;
            v.x = acc[i][j + 0]; v.y = acc[i][j + 1];
            v.z = acc[i][j + 2]; v.w = acc[i][j + 3];
            if (bias) {
                const float4 bv = *(const float4*)(bias + ccol0 + j);
                v.x += bv.x; v.y += bv.y; v.z += bv.z; v.w += bv.w;
            }
            if (relu) {
                v.x = fmaxf(v.x, 0.0f); v.y = fmaxf(v.y, 0.0f);
                v.z = fmaxf(v.z, 0.0f); v.w = fmaxf(v.w, 0.0f);
            }
            if (resid) {
                const float4 rv = *(const float4*)(resid + base + j);
                v.x += rv.x; v.y += rv.y; v.z += rv.z; v.w += rv.w;
            }
            *(float4*)(Cout + base + j) = v;
        }
    }
}

// ---------------- host orchestration ----------------------------------------
extern "C" void kernel_launch(void* const* d_in, const int* in_sizes, int n_in,
                              void* d_out, int out_size)
{
    const float* x   = (const float*)d_in[0];
    const float* Wq  = (const float*)d_in[1];
    const float* Wk  = (const float*)d_in[2];
    const float* Wv  = (const float*)d_in[3];
    const float* Wo  = (const float*)d_in[4];
    const float* bo  = (const float*)d_in[5];
    const float* W1  = (const float*)d_in[6];
    const float* b1  = (const float*)d_in[7];
    const float* W2  = (const float*)d_in[8];
    const float* b2  = (const float*)d_in[9];
    const float* g1  = (const float*)d_in[10];
    const float* be1 = (const float*)d_in[11];
    const float* g2  = (const float*)d_in[12];
    const float* be2 = (const float*)d_in[13];
    float* out = (float*)d_out;

    float *p_h, *p_attn, *p_x1, *p_ff1;
    cudaGetSymbolAddress((void**)&p_h,    g_h);
    cudaGetSymbolAddress((void**)&p_attn, g_attn);
    cudaGetSymbolAddress((void**)&p_x1,   g_x1);
    cudaGetSymbolAddress((void**)&p_ff1,  g_ff1);

    // 1. h = LN(x, g1, be1)
    ln_kernel<<<cBT, 128>>>(x, g1, be1, p_h);

    // 2. q,k,v projections (batched over b, head, which)
    {
        dim3 grid(1, cT / 64, cB * cH * 3);
        qkv_kernel<<<grid, 256>>>(p_h, Wq, Wk, Wv);
    }

    // 3. causal flash attention, one warp per query row -> g_attn (BT x C)
    {
        int warps = cB * cH * cT;            // 196608
        attn_kernel<<<warps / 8, 256>>>(p_attn);
    }

    // 4. x1 = x + attn @ Wo + bo
    {
        dim3 grid(cC / 128, cBT / 128);
        sgemm128<<<grid, 256>>>(p_attn, Wo, bo, x, p_x1, cBT, cC, cC, 0);
    }

    // 5. h2 = LN(x1, g2, be2)
    ln_kernel<<<cBT, 128>>>(p_x1, g2, be2, p_h);

    // 6. ff1 = relu(h2 @ W1 + b1)
    {
        dim3 grid(cDFF / 128, cBT / 128);
        sgemm128<<<grid, 256>>>(p_h, W1, b1, nullptr, p_ff1, cBT, cDFF, cC, 1);
    }

    // 7. out = x1 + ff1 @ W2 + b2
    {
        dim3 grid(cC / 128, cBT / 128);
        sgemm128<<<grid, 256>>>(p_ff1, W2, b2, p_x1, out, cBT, cC, cDFF, 0);
    }
}

// round 3
// speedup vs baseline: 2.2342x; 2.2342x over previous
#include <cuda_runtime.h>
#include <cuda_bf16.h>
#include <math.h>
#include <stdint.h>

// Problem constants
constexpr int cB   = 128;
constexpr int cT   = 256;
constexpr int cC   = 384;
constexpr int cH   = 6;
constexpr int cHS  = 64;
constexpr int cDFF = 1536;
constexpr int cBT  = cB * cT;          // 32768
constexpr int cQKV = 3 * cC;           // 1152

// ---------------- scratch (static device globals; no allocation) -------------
__device__ float g_h   [cBT * cC];          // LN output (reused for LN1 and LN2)
__device__ float g_wqkv[cC * cQKV];         // packed Wq|Wk|Wv, (C, 3*H*HS)
__device__ float g_qkv [cBT * cQKV];        // q|k|v, row = b*T+t, col = which*384+head*64+d
__device__ float g_attn[cBT * cC];          // attention output, (B,T,H*HS) layout
__device__ float g_x1  [cBT * cC];          // x + self-attention (residual 1)
__device__ float g_ff1 [cBT * cDFF];        // relu(h2 @ W1 + b1)

// ---------------- helpers ----------------------------------------------------
__device__ __forceinline__ uint32_t f2tf(float x) {
    uint32_t r;
    asm("cvt.rna.tf32.f32 %0, %1;" : "=r"(r) : "f"(x));
    return r;
}

__device__ __forceinline__ void mma_tf32(float c[4], const uint32_t a[4], const uint32_t b[2]) {
    asm volatile(
        "mma.sync.aligned.m16n8k8.row.col.f32.tf32.tf32.f32 "
        "{%0,%1,%2,%3}, {%4,%5,%6,%7}, {%8,%9}, {%0,%1,%2,%3};\n"
        : "+f"(c[0]), "+f"(c[1]), "+f"(c[2]), "+f"(c[3])
        : "r"(a[0]), "r"(a[1]), "r"(a[2]), "r"(a[3]), "r"(b[0]), "r"(b[1]));
}

// ---------------- LayerNorm: one block (128 thr) per row ---------------------
__global__ void ln_kernel(const float* __restrict__ x,
                          const float* __restrict__ g,
                          const float* __restrict__ b,
                          float* __restrict__ out)
{
    int row = blockIdx.x;
    const float* xr = x + (size_t)row * cC;
    float* orow     = out + (size_t)row * cC;
    int t = threadIdx.x;                // 0..127

    float v0 = xr[t], v1 = xr[t + 128], v2 = xr[t + 256];
    float s  = v0 + v1 + v2;

    __shared__ float sh[4];
    __shared__ float sh2[4];
    #pragma unroll
    for (int o = 16; o; o >>= 1) s += __shfl_xor_sync(0xffffffffu, s, o);
    if ((t & 31) == 0) sh[t >> 5] = s;
    __syncthreads();
    float mu = (sh[0] + sh[1] + sh[2] + sh[3]) * (1.0f / cC);

    float d0 = v0 - mu, d1 = v1 - mu, d2 = v2 - mu;
    float sq = d0 * d0 + d1 * d1 + d2 * d2;
    #pragma unroll
    for (int o = 16; o; o >>= 1) sq += __shfl_xor_sync(0xffffffffu, sq, o);
    if ((t & 31) == 0) sh2[t >> 5] = sq;
    __syncthreads();
    float var = (sh2[0] + sh2[1] + sh2[2] + sh2[3]) * (1.0f / cC);
    float r = rsqrtf(var + 1e-5f);

    orow[t]       = d0 * r * g[t]       + b[t];
    orow[t + 128] = d1 * r * g[t + 128] + b[t + 128];
    orow[t + 256] = d2 * r * g[t + 256] + b[t + 256];
}

// ---------------- pack Wq|Wk|Wv (H,C,HS) -> Wqkv (C, 3*H*HS) -----------------
__global__ void pack_qkv_kernel(const float* __restrict__ Wq,
                                const float* __restrict__ Wk,
                                const float* __restrict__ Wv,
                                float* __restrict__ Wqkv)
{
    int idx = blockIdx.x * 256 + threadIdx.x;
    if (idx >= cC * cQKV) return;
    int k   = idx / cQKV;
    int col = idx % cQKV;
    int which = col / cC;
    int rem   = col % cC;
    int head  = rem / cHS;
    int d     = rem % cHS;
    const float* W = (which == 0) ? Wq : (which == 1) ? Wk : Wv;
    Wqkv[idx] = W[((size_t)head * cC + k) * cHS + d];
}

// ---------------- tf32 tensor-core GEMM, 128x128x32 tiles --------------------
// A: M x K row-major, B: K x N row-major, C: M x N row-major.
// val = acc + bias[n]; if relu: max(val,0); if resid: += resid[m*N+n]
__global__ __launch_bounds__(256) void gemm_tf32(
    const float* __restrict__ A, const float* __restrict__ Bw,
    const float* __restrict__ bias, const float* __restrict__ resid,
    float* __restrict__ Cout,
    int M, int N, int K, int relu)
{
    __shared__ uint32_t As[128][36];    // [m][k], stride 36 -> conflict-free frags
    __shared__ uint32_t Bs[32][136];    // [k][n], stride 136 -> conflict-free frags

    int tid = threadIdx.x;
    int bx = blockIdx.x;                // N tile
    int by = blockIdx.y;                // M tile

    const float* Ab = A + (size_t)by * 128 * K;
    const float* Bb = Bw + (size_t)bx * 128;

    int wid = tid >> 5, lane = tid & 31;
    int wm = (wid & 1) * 64;            // warp m offset within tile (2 warps over M)
    int wn = (wid >> 1) * 32;           // warp n offset within tile (4 warps over N)
    int g  = lane >> 2;                 // groupID 0..7
    int tg = lane & 3;                  // thread-in-group 0..3

    // gmem load assignments
    int am = tid >> 1;                  // A row 0..127
    int ak = (tid & 1) * 16;            // A col base: 16 floats (4x float4) per thread
    int bk = tid >> 3;                  // B row 0..31
    int bn = (tid & 7) * 16;            // B col base: 16 floats per thread

    float acc[4][4][4];
    #pragma unroll
    for (int i = 0; i < 4; i++)
        #pragma unroll
        for (int j = 0; j < 4; j++)
            #pragma unroll
            for (int r = 0; r < 4; r++) acc[i][j][r] = 0.0f;

    for (int k0 = 0; k0 < K; k0 += 32) {
        // load A tile (convert to tf32)
        #pragma unroll
        for (int c = 0; c < 4; c++) {
            float4 v = *(const float4*)(Ab + (size_t)am * K + k0 + ak + c * 4);
            uint4 u;
            u.x = f2tf(v.x); u.y = f2tf(v.y); u.z = f2tf(v.z); u.w = f2tf(v.w);
            *(uint4*)&As[am][ak + c * 4] = u;
        }
        // load B tile
        #pragma unroll
        for (int c = 0; c < 4; c++) {
            float4 v = *(const float4*)(Bb + (size_t)(k0 + bk) * N + bn + c * 4);
            uint4 u;
            u.x = f2tf(v.x); u.y = f2tf(v.y); u.z = f2tf(v.z); u.w = f2tf(v.w);
            *(uint4*)&Bs[bk][bn + c * 4] = u;
        }
        __syncthreads();

        #pragma unroll
        for (int kk = 0; kk < 4; kk++) {
            uint32_t af[4][4], bf[4][2];
            #pragma unroll
            for (int i = 0; i < 4; i++) {
                int m = wm + i * 16;
                af[i][0] = As[m + g    ][kk * 8 + tg    ];
                af[i][1] = As[m + g + 8][kk * 8 + tg    ];
                af[i][2] = As[m + g    ][kk * 8 + tg + 4];
                af[i][3] = As[m + g + 8][kk * 8 + tg + 4];
            }
            #pragma unroll
            for (int j = 0; j < 4; j++) {
                int n = wn + j * 8 + g;
                bf[j][0] = Bs[kk * 8 + tg    ][n];
                bf[j][1] = Bs[kk * 8 + tg + 4][n];
            }
            #pragma unroll
            for (int i = 0; i < 4; i++)
                #pragma unroll
                for (int j = 0; j < 4; j++)
                    mma_tf32(acc[i][j], af[i], bf[j]);
        }
        __syncthreads();
    }

    // epilogue: each acc frag covers rows {r, r+8}, cols {c, c+1}
    #pragma unroll
    for (int i = 0; i < 4; i++) {
        #pragma unroll
        for (int j = 0; j < 4; j++) {
            int row = by * 128 + wm + i * 16 + g;
            int col = bx * 128 + wn + j * 8 + tg * 2;
            float2 bv = make_float2(0.f, 0.f);
            if (bias) bv = *(const float2*)(bias + col);

            float2 v0 = make_float2(acc[i][j][0] + bv.x, acc[i][j][1] + bv.y);
            float2 v1 = make_float2(acc[i][j][2] + bv.x, acc[i][j][3] + bv.y);
            if (relu) {
                v0.x = fmaxf(v0.x, 0.f); v0.y = fmaxf(v0.y, 0.f);
                v1.x = fmaxf(v1.x, 0.f); v1.y = fmaxf(v1.y, 0.f);
            }
            size_t o0 = (size_t)row * N + col;
            size_t o1 = (size_t)(row + 8) * N + col;
            if (resid) {
                float2 r0 = *(const float2*)(resid + o0);
                float2 r1 = *(const float2*)(resid + o1);
                v0.x += r0.x; v0.y += r0.y;
                v1.x += r1.x; v1.y += r1.y;
            }
            *(float2*)(Cout + o0) = v0;
            *(float2*)(Cout + o1) = v1;
        }
    }
}

// ---------------- causal attention: one warp per query row -------------------
// reads q/k/v from g_qkv (row stride 1152: q at +0, k at +384, v at +768)
__global__ void attn_kernel(float* __restrict__ out)
{
    int warp = (blockIdx.x * blockDim.x + threadIdx.x) >> 5;
    int lane = threadIdx.x & 31;
    int t  = warp % cT;
    int bh = warp / cT;            // b*H + head

    int bidx = bh / cH;
    int head = bh % cH;

    const float* qr = g_qkv + ((size_t)(bidx * cT + t)) * cQKV + head * cHS;
    const float* kb = g_qkv + ((size_t)(bidx * cT)) * cQKV + cC + head * cHS;
    const float* vb = kb + cC;     // v block is +384 past k block

    float q0 = qr[lane], q1 = qr[lane + 32];

    float m = -1e30f, l = 0.0f, a0 = 0.0f, a1 = 0.0f;
    const float scale = 0.125f;    // 1/sqrt(64)

    for (int s = 0; s <= t; s++) {
        const float* kr = kb + (size_t)s * cQKV;
        float p = q0 * kr[lane] + q1 * kr[lane + 32];
        #pragma unroll
        for (int o = 16; o; o >>= 1) p += __shfl_xor_sync(0xffffffffu, p, o);
        p *= scale;
        float nm = fmaxf(m, p);
        float corr = __expf(m - nm);
        float e = __expf(p - nm);
        const float* vr = vb + (size_t)s * cQKV;
        a0 = a0 * corr + e * vr[lane];
        a1 = a1 * corr + e * vr[lane + 32];
        l = l * corr + e;
        m = nm;
    }

    float inv = 1.0f / l;
    size_t base = ((size_t)(bidx * cT + t)) * cC + head * cHS;
    out[base + lane]      = a0 * inv;
    out[base + lane + 32] = a1 * inv;
}

// ---------------- host orchestration ----------------------------------------
extern "C" void kernel_launch(void* const* d_in, const int* in_sizes, int n_in,
                              void* d_out, int out_size)
{
    const float* x   = (const float*)d_in[0];
    const float* Wq  = (const float*)d_in[1];
    const float* Wk  = (const float*)d_in[2];
    const float* Wv  = (const float*)d_in[3];
    const float* Wo  = (const float*)d_in[4];
    const float* bo  = (const float*)d_in[5];
    const float* W1  = (const float*)d_in[6];
    const float* b1  = (const float*)d_in[7];
    const float* W2  = (const float*)d_in[8];
    const float* b2  = (const float*)d_in[9];
    const float* g1  = (const float*)d_in[10];
    const float* be1 = (const float*)d_in[11];
    const float* g2  = (const float*)d_in[12];
    const float* be2 = (const float*)d_in[13];
    float* out = (float*)d_out;

    float *p_h, *p_wqkv, *p_qkv, *p_attn, *p_x1, *p_ff1;
    cudaGetSymbolAddress((void**)&p_h,    g_h);
    cudaGetSymbolAddress((void**)&p_wqkv, g_wqkv);
    cudaGetSymbolAddress((void**)&p_qkv,  g_qkv);
    cudaGetSymbolAddress((void**)&p_attn, g_attn);
    cudaGetSymbolAddress((void**)&p_x1,   g_x1);
    cudaGetSymbolAddress((void**)&p_ff1,  g_ff1);

    // 1. h = LN(x, g1, be1)
    ln_kernel<<<cBT, 128>>>(x, g1, be1, p_h);

    // 2. pack Wq|Wk|Wv -> Wqkv (C x 1152)
    pack_qkv_kernel<<<(cC * cQKV + 255) / 256, 256>>>(Wq, Wk, Wv, p_wqkv);

    // 3. qkv = h @ Wqkv   (BT x 1152)
    {
        dim3 grid(cQKV / 128, cBT / 128);
        gemm_tf32<<<grid, 256>>>(p_h, p_wqkv, nullptr, nullptr, p_qkv, cBT, cQKV, cC, 0);
    }

    // 4. causal flash attention -> g_attn (BT x C)
    {
        int warps = cB * cH * cT;            // 196608
        attn_kernel<<<warps / 8, 256>>>(p_attn);
    }

    // 5. x1 = x + attn @ Wo + bo
    {
        dim3 grid(cC / 128, cBT / 128);
        gemm_tf32<<<grid, 256>>>(p_attn, Wo, bo, x, p_x1, cBT, cC, cC, 0);
    }

    // 6. h2 = LN(x1, g2, be2)
    ln_kernel<<<cBT, 128>>>(p_x1, g2, be2, p_h);

    // 7. ff1 = relu(h2 @ W1 + b1)
    {
        dim3 grid(cDFF / 128, cBT / 128);
        gemm_tf32<<<grid, 256>>>(p_h, W1, b1, nullptr, p_ff1, cBT, cDFF, cC, 1);
    }

    // 8. out = x1 + ff1 @ W2 + b2
    {
        dim3 grid(cC / 128, cBT / 128);
        gemm_tf32<<<grid, 256>>>(p_ff1, W2, b2, p_x1, out, cBT, cC, cDFF, 0);
    }
}

// round 4
// speedup vs baseline: 4.3928x; 1.9662x over previous
#include <cuda_runtime.h>
#include <cuda_bf16.h>
#include <math.h>
#include <stdint.h>

// Problem constants
constexpr int cB   = 128;
constexpr int cT   = 256;
constexpr int cC   = 384;
constexpr int cH   = 6;
constexpr int cHS  = 64;
constexpr int cDFF = 1536;
constexpr int cBT  = cB * cT;          // 32768
constexpr int cQKV = 3 * cC;           // 1152

// ---------------- scratch (static device globals; no allocation) -------------
__device__ float g_h   [cBT * cC];
__device__ float g_wqkv[cC * cQKV];
__device__ float g_qkv [cBT * cQKV];
__device__ float g_attn[cBT * cC];
__device__ float g_x1  [cBT * cC];
__device__ float g_ff1 [cBT * cDFF];

// ---------------- helpers ----------------------------------------------------
__device__ __forceinline__ uint32_t f2tf(float x) {
    uint32_t r;
    asm("cvt.rna.tf32.f32 %0, %1;" : "=r"(r) : "f"(x));
    return r;
}

__device__ __forceinline__ void mma_tf32(float c[4], const uint32_t a[4], const uint32_t b[2]) {
    asm volatile(
        "mma.sync.aligned.m16n8k8.row.col.f32.tf32.tf32.f32 "
        "{%0,%1,%2,%3}, {%4,%5,%6,%7}, {%8,%9}, {%0,%1,%2,%3};\n"
        : "+f"(c[0]), "+f"(c[1]), "+f"(c[2]), "+f"(c[3])
        : "r"(a[0]), "r"(a[1]), "r"(a[2]), "r"(a[3]), "r"(b[0]), "r"(b[1]));
}

// ---------------- LayerNorm: one block (128 thr) per row ---------------------
__global__ void ln_kernel(const float* __restrict__ x,
                          const float* __restrict__ g,
                          const float* __restrict__ b,
                          float* __restrict__ out)
{
    int row = blockIdx.x;
    const float* xr = x + (size_t)row * cC;
    float* orow     = out + (size_t)row * cC;
    int t = threadIdx.x;

    float v0 = xr[t], v1 = xr[t + 128], v2 = xr[t + 256];
    float s  = v0 + v1 + v2;

    __shared__ float sh[4];
    __shared__ float sh2[4];
    #pragma unroll
    for (int o = 16; o; o >>= 1) s += __shfl_xor_sync(0xffffffffu, s, o);
    if ((t & 31) == 0) sh[t >> 5] = s;
    __syncthreads();
    float mu = (sh[0] + sh[1] + sh[2] + sh[3]) * (1.0f / cC);

    float d0 = v0 - mu, d1 = v1 - mu, d2 = v2 - mu;
    float sq = d0 * d0 + d1 * d1 + d2 * d2;
    #pragma unroll
    for (int o = 16; o; o >>= 1) sq += __shfl_xor_sync(0xffffffffu, sq, o);
    if ((t & 31) == 0) sh2[t >> 5] = sq;
    __syncthreads();
    float var = (sh2[0] + sh2[1] + sh2[2] + sh2[3]) * (1.0f / cC);
    float r = rsqrtf(var + 1e-5f);

    orow[t]       = d0 * r * g[t]       + b[t];
    orow[t + 128] = d1 * r * g[t + 128] + b[t + 128];
    orow[t + 256] = d2 * r * g[t + 256] + b[t + 256];
}

// ---------------- pack Wq|Wk|Wv (H,C,HS) -> Wqkv (C, 3*H*HS) -----------------
__global__ void pack_qkv_kernel(const float* __restrict__ Wq,
                                const float* __restrict__ Wk,
                                const float* __restrict__ Wv,
                                float* __restrict__ Wqkv)
{
    int idx = blockIdx.x * 256 + threadIdx.x;
    if (idx >= cC * cQKV) return;
    int k   = idx / cQKV;
    int col = idx % cQKV;
    int which = col / cC;
    int rem   = col % cC;
    int head  = rem / cHS;
    int d     = rem % cHS;
    const float* W = (which == 0) ? Wq : (which == 1) ? Wk : Wv;
    Wqkv[idx] = W[((size_t)head * cC + k) * cHS + d];
}

// ---------------- tf32 tensor-core GEMM, 128x128x32 tiles --------------------
__global__ __launch_bounds__(256) void gemm_tf32(
    const float* __restrict__ A, const float* __restrict__ Bw,
    const float* __restrict__ bias, const float* __restrict__ resid,
    float* __restrict__ Cout,
    int M, int N, int K, int relu)
{
    __shared__ uint32_t As[128][36];
    __shared__ uint32_t Bs[32][136];

    int tid = threadIdx.x;
    int bx = blockIdx.x;
    int by = blockIdx.y;

    const float* Ab = A + (size_t)by * 128 * K;
    const float* Bb = Bw + (size_t)bx * 128;

    int wid = tid >> 5, lane = tid & 31;
    int wm = (wid & 1) * 64;
    int wn = (wid >> 1) * 32;
    int g  = lane >> 2;
    int tg = lane & 3;

    int am = tid >> 1;
    int ak = (tid & 1) * 16;
    int bk = tid >> 3;
    int bn = (tid & 7) * 16;

    float acc[4][4][4];
    #pragma unroll
    for (int i = 0; i < 4; i++)
        #pragma unroll
        for (int j = 0; j < 4; j++)
            #pragma unroll
            for (int r = 0; r < 4; r++) acc[i][j][r] = 0.0f;

    for (int k0 = 0; k0 < K; k0 += 32) {
        #pragma unroll
        for (int c = 0; c < 4; c++) {
            float4 v = *(const float4*)(Ab + (size_t)am * K + k0 + ak + c * 4);
            uint4 u;
            u.x = f2tf(v.x); u.y = f2tf(v.y); u.z = f2tf(v.z); u.w = f2tf(v.w);
            *(uint4*)&As[am][ak + c * 4] = u;
        }
        #pragma unroll
        for (int c = 0; c < 4; c++) {
            float4 v = *(const float4*)(Bb + (size_t)(k0 + bk) * N + bn + c * 4);
            uint4 u;
            u.x = f2tf(v.x); u.y = f2tf(v.y); u.z = f2tf(v.z); u.w = f2tf(v.w);
            *(uint4*)&Bs[bk][bn + c * 4] = u;
        }
        __syncthreads();

        #pragma unroll
        for (int kk = 0; kk < 4; kk++) {
            uint32_t af[4][4], bf[4][2];
            #pragma unroll
            for (int i = 0; i < 4; i++) {
                int m = wm + i * 16;
                af[i][0] = As[m + g    ][kk * 8 + tg    ];
                af[i][1] = As[m + g + 8][kk * 8 + tg    ];
                af[i][2] = As[m + g    ][kk * 8 + tg + 4];
                af[i][3] = As[m + g + 8][kk * 8 + tg + 4];
            }
            #pragma unroll
            for (int j = 0; j < 4; j++) {
                int n = wn + j * 8 + g;
                bf[j][0] = Bs[kk * 8 + tg    ][n];
                bf[j][1] = Bs[kk * 8 + tg + 4][n];
            }
            #pragma unroll
            for (int i = 0; i < 4; i++)
                #pragma unroll
                for (int j = 0; j < 4; j++)
                    mma_tf32(acc[i][j], af[i], bf[j]);
        }
        __syncthreads();
    }

    #pragma unroll
    for (int i = 0; i < 4; i++) {
        #pragma unroll
        for (int j = 0; j < 4; j++) {
            int row = by * 128 + wm + i * 16 + g;
            int col = bx * 128 + wn + j * 8 + tg * 2;
            float2 bv = make_float2(0.f, 0.f);
            if (bias) bv = *(const float2*)(bias + col);

            float2 v0 = make_float2(acc[i][j][0] + bv.x, acc[i][j][1] + bv.y);
            float2 v1 = make_float2(acc[i][j][2] + bv.x, acc[i][j][3] + bv.y);
            if (relu) {
                v0.x = fmaxf(v0.x, 0.f); v0.y = fmaxf(v0.y, 0.f);
                v1.x = fmaxf(v1.x, 0.f); v1.y = fmaxf(v1.y, 0.f);
            }
            size_t o0 = (size_t)row * N + col;
            size_t o1 = (size_t)(row + 8) * N + col;
            if (resid) {
                float2 r0 = *(const float2*)(resid + o0);
                float2 r1 = *(const float2*)(resid + o1);
                v0.x += r0.x; v0.y += r0.y;
                v1.x += r1.x; v1.y += r1.y;
            }
            *(float2*)(Cout + o0) = v0;
            *(float2*)(Cout + o1) = v1;
        }
    }
}

// ---------------- flash attention, tensor-core tiles -------------------------
// Block: (qtile, head, b). 128 threads = 4 warps x 16 query rows.
// Smem strides: Q/K/S = 68, V = 72 (bank-conflict-free frag loads).
constexpr int QS_STRIDE = 68;
constexpr int VS_STRIDE = 72;
constexpr int ATTN_SMEM_WORDS = 3 * 64 * QS_STRIDE + 64 * VS_STRIDE + 192;
constexpr int ATTN_SMEM_BYTES = ATTN_SMEM_WORDS * 4;

__global__ __launch_bounds__(128) void attn_flash(
    const float* __restrict__ qkv, float* __restrict__ out)
{
    extern __shared__ float smem_f[];
    uint32_t* Qs = (uint32_t*)smem_f;                 // [64][68] tf32 (Q * scale)
    uint32_t* Ks = Qs + 64 * QS_STRIDE;               // [64][68] tf32, row=j col=d
    float*    Ss = (float*)(Ks + 64 * QS_STRIDE);     // [64][68] f32 scores / tf32 P
    uint32_t* SsU = (uint32_t*)Ss;
    uint32_t* Vs = (uint32_t*)(Ss + 64 * QS_STRIDE);  // [64][72] tf32, row=s col=d
    float* row_m = (float*)(Vs + 64 * VS_STRIDE);
    float* row_l = row_m + 64;
    float* row_c = row_l + 64;

    int qt = blockIdx.x, head = blockIdx.y, b = blockIdx.z;
    int tid = threadIdx.x;
    int wid = tid >> 5, lane = tid & 31;
    int g = lane >> 2, tg = lane & 3;
    int wm = wid * 16;

    const float* qbase = qkv + (size_t)(b * cT + qt * 64) * cQKV + head * cHS;
    const float* kbase = qkv + (size_t)(b * cT) * cQKV + cC + head * cHS;
    const float* vbase = kbase + cC;

    // load Q tile (scaled by 1/sqrt(HS)=0.125), convert to tf32
    {
        int r = tid >> 1, c0 = (tid & 1) * 32;
        const float* src = qbase + (size_t)r * cQKV + c0;
        uint32_t* dst = Qs + r * QS_STRIDE + c0;
        #pragma unroll
        for (int i = 0; i < 8; i++) {
            float4 v = *(const float4*)(src + i * 4);
            dst[i * 4 + 0] = f2tf(v.x * 0.125f);
            dst[i * 4 + 1] = f2tf(v.y * 0.125f);
            dst[i * 4 + 2] = f2tf(v.z * 0.125f);
            dst[i * 4 + 3] = f2tf(v.w * 0.125f);
        }
    }
    if (tid < 64) { row_m[tid] = -1e30f; row_l[tid] = 0.0f; }
    __syncthreads();

    // cache Q frags in registers (constant across key tiles)
    uint32_t qf[8][4];
    #pragma unroll
    for (int kk = 0; kk < 8; kk++) {
        qf[kk][0] = Qs[(wm + g    ) * QS_STRIDE + kk * 8 + tg    ];
        qf[kk][1] = Qs[(wm + g + 8) * QS_STRIDE + kk * 8 + tg    ];
        qf[kk][2] = Qs[(wm + g    ) * QS_STRIDE + kk * 8 + tg + 4];
        qf[kk][3] = Qs[(wm + g + 8) * QS_STRIDE + kk * 8 + tg + 4];
    }

    float o[8][4];
    #pragma unroll
    for (int j = 0; j < 8; j++)
        #pragma unroll
        for (int r = 0; r < 4; r++) o[j][r] = 0.0f;

    int ntiles = qt + 1;
    for (int ti = 0; ti < ntiles; ti++) {
        int s0 = ti * 64;

        // load K and V tiles
        {
            int r = tid >> 1, c0 = (tid & 1) * 32;
            const float* ksrc = kbase + (size_t)(s0 + r) * cQKV + c0;
            const float* vsrc = vbase + (size_t)(s0 + r) * cQKV + c0;
            uint32_t* kdst = Ks + r * QS_STRIDE + c0;
            uint32_t* vdst = Vs + r * VS_STRIDE + c0;
            #pragma unroll
            for (int i = 0; i < 8; i++) {
                float4 kv = *(const float4*)(ksrc + i * 4);
                kdst[i * 4 + 0] = f2tf(kv.x);
                kdst[i * 4 + 1] = f2tf(kv.y);
                kdst[i * 4 + 2] = f2tf(kv.z);
                kdst[i * 4 + 3] = f2tf(kv.w);
                float4 vv = *(const float4*)(vsrc + i * 4);
                vdst[i * 4 + 0] = f2tf(vv.x);
                vdst[i * 4 + 1] = f2tf(vv.y);
                vdst[i * 4 + 2] = f2tf(vv.z);
                vdst[i * 4 + 3] = f2tf(vv.w);
            }
        }
        __syncthreads();

        // S = Q @ K^T  (warp computes its 16 rows x 64 cols)
        #pragma unroll
        for (int jn = 0; jn < 8; jn++) {
            float sc[4] = {0.f, 0.f, 0.f, 0.f};
            #pragma unroll
            for (int kk = 0; kk < 8; kk++) {
                uint32_t bf[2];
                bf[0] = Ks[(jn * 8 + g) * QS_STRIDE + kk * 8 + tg    ];
                bf[1] = Ks[(jn * 8 + g) * QS_STRIDE + kk * 8 + tg + 4];
                mma_tf32(sc, qf[kk], bf);
            }
            Ss[(wm + g    ) * QS_STRIDE + jn * 8 + 2 * tg    ] = sc[0];
            Ss[(wm + g    ) * QS_STRIDE + jn * 8 + 2 * tg + 1] = sc[1];
            Ss[(wm + g + 8) * QS_STRIDE + jn * 8 + 2 * tg    ] = sc[2];
            Ss[(wm + g + 8) * QS_STRIDE + jn * 8 + 2 * tg + 1] = sc[3];
        }
        __syncwarp();

        // online softmax on warp-owned rows (2 lanes per row)
        {
            int rloc = wm + (lane >> 1);
            int half = lane & 1;
            float* srow = Ss + rloc * QS_STRIDE + half * 32;
            int ig = qt * 64 + rloc;
            int jbase = s0 + half * 32;
            bool diag = (ti == qt);

            float mx = -1e30f;
            if (diag) {
                #pragma unroll
                for (int c = 0; c < 32; c++) {
                    float v = (jbase + c <= ig) ? srow[c] : -1e30f;
                    srow[c] = v;
                    mx = fmaxf(mx, v);
                }
            } else {
                #pragma unroll
                for (int c = 0; c < 32; c++) mx = fmaxf(mx, srow[c]);
            }
            mx = fmaxf(mx, __shfl_xor_sync(0xffffffffu, mx, 1));

            float om = row_m[rloc];
            float nm = fmaxf(om, mx);
            float corr = __expf(om - nm);

            float se = 0.0f;
            uint32_t* prow = SsU + rloc * QS_STRIDE + half * 32;
            #pragma unroll
            for (int c = 0; c < 32; c++) {
                float e = __expf(srow[c] - nm);
                prow[c] = f2tf(e);
                se += e;
            }
            se += __shfl_xor_sync(0xffffffffu, se, 1);

            if (half == 0) {
                row_m[rloc] = nm;
                row_l[rloc] = row_l[rloc] * corr + se;
                row_c[rloc] = corr;
            }
        }
        __syncwarp();

        // rescale O accum, then O += P @ V
        {
            float c0 = row_c[wm + g], c1 = row_c[wm + g + 8];
            #pragma unroll
            for (int j = 0; j < 8; j++) {
                o[j][0] *= c0; o[j][1] *= c0;
                o[j][2] *= c1; o[j][3] *= c1;
            }
        }
        #pragma unroll
        for (int kk = 0; kk < 8; kk++) {
            uint32_t pf[4];
            pf[0] = SsU[(wm + g    ) * QS_STRIDE + kk * 8 + tg    ];
            pf[1] = SsU[(wm + g + 8) * QS_STRIDE + kk * 8 + tg    ];
            pf[2] = SsU[(wm + g    ) * QS_STRIDE + kk * 8 + tg + 4];
            pf[3] = SsU[(wm + g + 8) * QS_STRIDE + kk * 8 + tg + 4];
            #pragma unroll
            for (int j = 0; j < 8; j++) {
                uint32_t bf[2];
                bf[0] = Vs[(kk * 8 + tg    ) * VS_STRIDE + j * 8 + g];
                bf[1] = Vs[(kk * 8 + tg + 4) * VS_STRIDE + j * 8 + g];
                mma_tf32(o[j], pf, bf);
            }
        }
        __syncthreads();   // all warps done with Ks/Vs before next tile load
    }

    // epilogue: divide by l, write to g_attn (BT x C), cols head*64 + ...
    {
        float inv0 = 1.0f / row_l[wm + g];
        float inv1 = 1.0f / row_l[wm + g + 8];
        int r0 = b * cT + qt * 64 + wm + g;
        size_t base0 = (size_t)r0 * cC + head * cHS;
        size_t base1 = (size_t)(r0 + 8) * cC + head * cHS;
        #pragma unroll
        for (int j = 0; j < 8; j++) {
            int col = j * 8 + 2 * tg;
            float2 v0 = make_float2(o[j][0] * inv0, o[j][1] * inv0);
            float2 v1 = make_float2(o[j][2] * inv1, o[j][3] * inv1);
            *(float2*)(out + base0 + col) = v0;
            *(float2*)(out + base1 + col) = v1;
        }
    }
}

// ---------------- host orchestration ----------------------------------------
extern "C" void kernel_launch(void* const* d_in, const int* in_sizes, int n_in,
                              void* d_out, int out_size)
{
    const float* x   = (const float*)d_in[0];
    const float* Wq  = (const float*)d_in[1];
    const float* Wk  = (const float*)d_in[2];
    const float* Wv  = (const float*)d_in[3];
    const float* Wo  = (const float*)d_in[4];
    const float* bo  = (const float*)d_in[5];
    const float* W1  = (const float*)d_in[6];
    const float* b1  = (const float*)d_in[7];
    const float* W2  = (const float*)d_in[8];
    const float* b2  = (const float*)d_in[9];
    const float* g1  = (const float*)d_in[10];
    const float* be1 = (const float*)d_in[11];
    const float* g2  = (const float*)d_in[12];
    const float* be2 = (const float*)d_in[13];
    float* out = (float*)d_out;

    float *p_h, *p_wqkv, *p_qkv, *p_attn, *p_x1, *p_ff1;
    cudaGetSymbolAddress((void**)&p_h,    g_h);
    cudaGetSymbolAddress((void**)&p_wqkv, g_wqkv);
    cudaGetSymbolAddress((void**)&p_qkv,  g_qkv);
    cudaGetSymbolAddress((void**)&p_attn, g_attn);
    cudaGetSymbolAddress((void**)&p_x1,   g_x1);
    cudaGetSymbolAddress((void**)&p_ff1,  g_ff1);

    cudaFuncSetAttribute(attn_flash,
        cudaFuncAttributeMaxDynamicSharedMemorySize, ATTN_SMEM_BYTES);

    // 1. h = LN(x, g1, be1)
    ln_kernel<<<cBT, 128>>>(x, g1, be1, p_h);

    // 2. pack Wq|Wk|Wv -> Wqkv (C x 1152)
    pack_qkv_kernel<<<(cC * cQKV + 255) / 256, 256>>>(Wq, Wk, Wv, p_wqkv);

    // 3. qkv = h @ Wqkv   (BT x 1152)
    {
        dim3 grid(cQKV / 128, cBT / 128);
        gemm_tf32<<<grid, 256>>>(p_h, p_wqkv, nullptr, nullptr, p_qkv, cBT, cQKV, cC, 0);
    }

    // 4. flash attention -> g_attn (BT x C)
    {
        dim3 grid(cT / 64, cH, cB);
        attn_flash<<<grid, 128, ATTN_SMEM_BYTES>>>(p_qkv, p_attn);
    }

    // 5. x1 = x + attn @ Wo + bo
    {
        dim3 grid(cC / 128, cBT / 128);
        gemm_tf32<<<grid, 256>>>(p_attn, Wo, bo, x, p_x1, cBT, cC, cC, 0);
    }

    // 6. h2 = LN(x1, g2, be2)
    ln_kernel<<<cBT, 128>>>(p_x1, g2, be2, p_h);

    // 7. ff1 = relu(h2 @ W1 + b1)
    {
        dim3 grid(cDFF / 128, cBT / 128);
        gemm_tf32<<<grid, 256>>>(p_h, W1, b1, nullptr, p_ff1, cBT, cDFF, cC, 1);
    }

    // 8. out = x1 + ff1 @ W2 + b2
    {
        dim3 grid(cC / 128, cBT / 128);
        gemm_tf32<<<grid, 256>>>(p_ff1, W2, b2, p_x1, out, cBT, cC, cDFF, 0);
    }
}

// round 5
// speedup vs baseline: 4.7261x; 1.0759x over previous
#include <cuda_runtime.h>
#include <cuda_bf16.h>
#include <math.h>
#include <stdint.h>

// Problem constants
constexpr int cB   = 128;
constexpr int cT   = 256;
constexpr int cC   = 384;
constexpr int cH   = 6;
constexpr int cHS  = 64;
constexpr int cDFF = 1536;
constexpr int cBT  = cB * cT;          // 32768
constexpr int cQKV = 3 * cC;           // 1152

// ---------------- scratch (static device globals; no allocation) -------------
__device__ float g_h   [cBT * cC];
__device__ float g_wqkv[cC * cQKV];
__device__ float g_qkv [cBT * cQKV];
__device__ float g_attn[cBT * cC];
__device__ float g_x1  [cBT * cC];
__device__ float g_ff1 [cBT * cDFF];

// ---------------- helpers ----------------------------------------------------
__device__ __forceinline__ uint32_t f2tf(float x) {
    uint32_t r;
    asm("cvt.rna.tf32.f32 %0, %1;" : "=r"(r) : "f"(x));
    return r;
}

__device__ __forceinline__ void mma_tf32(float c[4], const uint32_t a[4], const uint32_t b[2]) {
    asm volatile(
        "mma.sync.aligned.m16n8k8.row.col.f32.tf32.tf32.f32 "
        "{%0,%1,%2,%3}, {%4,%5,%6,%7}, {%8,%9}, {%0,%1,%2,%3};\n"
        : "+f"(c[0]), "+f"(c[1]), "+f"(c[2]), "+f"(c[3])
        : "r"(a[0]), "r"(a[1]), "r"(a[2]), "r"(a[3]), "r"(b[0]), "r"(b[1]));
}

__device__ __forceinline__ void cpasync16(uint32_t dst_smem, const void* src) {
    asm volatile("cp.async.ca.shared.global [%0], [%1], 16;\n"
                 :: "r"(dst_smem), "l"(src));
}
__device__ __forceinline__ void cpasync_commit() {
    asm volatile("cp.async.commit_group;\n");
}
__device__ __forceinline__ void cpasync_wait0() {
    asm volatile("cp.async.wait_group 0;\n");
}

// ---------------- LayerNorm: one block (128 thr) per row ---------------------
__global__ void ln_kernel(const float* __restrict__ x,
                          const float* __restrict__ g,
                          const float* __restrict__ b,
                          float* __restrict__ out)
{
    int row = blockIdx.x;
    const float* xr = x + (size_t)row * cC;
    float* orow     = out + (size_t)row * cC;
    int t = threadIdx.x;

    float v0 = xr[t], v1 = xr[t + 128], v2 = xr[t + 256];
    float s  = v0 + v1 + v2;

    __shared__ float sh[4];
    __shared__ float sh2[4];
    #pragma unroll
    for (int o = 16; o; o >>= 1) s += __shfl_xor_sync(0xffffffffu, s, o);
    if ((t & 31) == 0) sh[t >> 5] = s;
    __syncthreads();
    float mu = (sh[0] + sh[1] + sh[2] + sh[3]) * (1.0f / cC);

    float d0 = v0 - mu, d1 = v1 - mu, d2 = v2 - mu;
    float sq = d0 * d0 + d1 * d1 + d2 * d2;
    #pragma unroll
    for (int o = 16; o; o >>= 1) sq += __shfl_xor_sync(0xffffffffu, sq, o);
    if ((t & 31) == 0) sh2[t >> 5] = sq;
    __syncthreads();
    float var = (sh2[0] + sh2[1] + sh2[2] + sh2[3]) * (1.0f / cC);
    float r = rsqrtf(var + 1e-5f);

    orow[t]       = d0 * r * g[t]       + b[t];
    orow[t + 128] = d1 * r * g[t + 128] + b[t + 128];
    orow[t + 256] = d2 * r * g[t + 256] + b[t + 256];
}

// ---------------- pack Wq|Wk|Wv (H,C,HS) -> Wqkv (C, 3*H*HS) -----------------
__global__ void pack_qkv_kernel(const float* __restrict__ Wq,
                                const float* __restrict__ Wk,
                                const float* __restrict__ Wv,
                                float* __restrict__ Wqkv)
{
    int idx = blockIdx.x * 256 + threadIdx.x;
    if (idx >= cC * cQKV) return;
    int k   = idx / cQKV;
    int col = idx % cQKV;
    int which = col / cC;
    int rem   = col % cC;
    int head  = rem / cHS;
    int d     = rem % cHS;
    const float* W = (which == 0) ? Wq : (which == 1) ? Wk : Wv;
    Wqkv[idx] = W[((size_t)head * cC + k) * cHS + d];
}

// ---------------- tf32 GEMM, 128x128x32 tiles, cp.async double-buffered ------
constexpr int A_STRIDE = 36;
constexpr int B_STRIDE = 136;
constexpr int A_TILE_W = 128 * A_STRIDE;             // words per A stage
constexpr int B_TILE_W = 32 * B_STRIDE;              // words per B stage
constexpr int GEMM_SMEM_BYTES = 2 * (A_TILE_W + B_TILE_W) * 4;   // 71680

__global__ __launch_bounds__(256) void gemm_tf32(
    const float* __restrict__ A, const float* __restrict__ Bw,
    const float* __restrict__ bias, const float* __restrict__ resid,
    float* __restrict__ Cout,
    int M, int N, int K, int relu)
{
    extern __shared__ float sm[];
    float* As = sm;                         // [2][128][36]
    float* Bs = sm + 2 * A_TILE_W;          // [2][32][136]

    int tid = threadIdx.x;
    int bx = blockIdx.x;
    int by = blockIdx.y;

    const float* Ab = A + (size_t)by * 128 * K;
    const float* Bb = Bw + (size_t)bx * 128;

    int wid = tid >> 5, lane = tid & 31;
    int wm = (wid & 1) * 64;
    int wn = (wid >> 1) * 32;
    int g  = lane >> 2;
    int tg = lane & 3;

    // cp.async assignments: 4x16B per thread for each of A and B
    int am = tid >> 1;                      // A row 0..127
    int ak = (tid & 1) * 16;                // A col base (16 floats via 4x16B)
    int bk = tid >> 3;                      // B row 0..31
    int bn = (tid & 7) * 16;                // B col base

    uint32_t smemA = (uint32_t)__cvta_generic_to_shared(As);
    uint32_t smemB = (uint32_t)__cvta_generic_to_shared(Bs);

    float acc[4][4][4];
    #pragma unroll
    for (int i = 0; i < 4; i++)
        #pragma unroll
        for (int j = 0; j < 4; j++)
            #pragma unroll
            for (int r = 0; r < 4; r++) acc[i][j][r] = 0.0f;

    int niter = K >> 5;

    // prefetch stage 0
    {
        const float* asrc = Ab + (size_t)am * K + ak;
        const float* bsrc = Bb + (size_t)bk * N + bn;
        uint32_t adst = smemA + (am * A_STRIDE + ak) * 4;
        uint32_t bdst = smemB + (bk * B_STRIDE + bn) * 4;
        #pragma unroll
        for (int c = 0; c < 4; c++) {
            cpasync16(adst + c * 16, asrc + c * 4);
            cpasync16(bdst + c * 16, bsrc + c * 4);
        }
        cpasync_commit();
    }

    int buf = 0;
    for (int it = 0; it < niter; it++) {
        cpasync_wait0();
        __syncthreads();

        if (it + 1 < niter) {
            int k0n = (it + 1) << 5;
            int nb = buf ^ 1;
            const float* asrc = Ab + (size_t)am * K + k0n + ak;
            const float* bsrc = Bb + (size_t)(k0n + bk) * N + bn;
            uint32_t adst = smemA + (nb * A_TILE_W + am * A_STRIDE + ak) * 4;
            uint32_t bdst = smemB + (nb * B_TILE_W + bk * B_STRIDE + bn) * 4;
            #pragma unroll
            for (int c = 0; c < 4; c++) {
                cpasync16(adst + c * 16, asrc + c * 4);
                cpasync16(bdst + c * 16, bsrc + c * 4);
            }
            cpasync_commit();
        }

        const float* Ac = As + buf * A_TILE_W;
        const float* Bc = Bs + buf * B_TILE_W;

        #pragma unroll
        for (int kk = 0; kk < 4; kk++) {
            uint32_t af[4][4], bf[4][2];
            #pragma unroll
            for (int i = 0; i < 4; i++) {
                int m = wm + i * 16;
                af[i][0] = f2tf(Ac[(m + g    ) * A_STRIDE + kk * 8 + tg    ]);
                af[i][1] = f2tf(Ac[(m + g + 8) * A_STRIDE + kk * 8 + tg    ]);
                af[i][2] = f2tf(Ac[(m + g    ) * A_STRIDE + kk * 8 + tg + 4]);
                af[i][3] = f2tf(Ac[(m + g + 8) * A_STRIDE + kk * 8 + tg + 4]);
            }
            #pragma unroll
            for (int j = 0; j < 4; j++) {
                int n = wn + j * 8 + g;
                bf[j][0] = f2tf(Bc[(kk * 8 + tg    ) * B_STRIDE + n]);
                bf[j][1] = f2tf(Bc[(kk * 8 + tg + 4) * B_STRIDE + n]);
            }
            #pragma unroll
            for (int i = 0; i < 4; i++)
                #pragma unroll
                for (int j = 0; j < 4; j++)
                    mma_tf32(acc[i][j], af[i], bf[j]);
        }
        __syncthreads();
        buf ^= 1;
    }

    #pragma unroll
    for (int i = 0; i < 4; i++) {
        #pragma unroll
        for (int j = 0; j < 4; j++) {
            int row = by * 128 + wm + i * 16 + g;
            int col = bx * 128 + wn + j * 8 + tg * 2;
            float2 bv = make_float2(0.f, 0.f);
            if (bias) bv = *(const float2*)(bias + col);

            float2 v0 = make_float2(acc[i][j][0] + bv.x, acc[i][j][1] + bv.y);
            float2 v1 = make_float2(acc[i][j][2] + bv.x, acc[i][j][3] + bv.y);
            if (relu) {
                v0.x = fmaxf(v0.x, 0.f); v0.y = fmaxf(v0.y, 0.f);
                v1.x = fmaxf(v1.x, 0.f); v1.y = fmaxf(v1.y, 0.f);
            }
            size_t o0 = (size_t)row * N + col;
            size_t o1 = (size_t)(row + 8) * N + col;
            if (resid) {
                float2 r0 = *(const float2*)(resid + o0);
                float2 r1 = *(const float2*)(resid + o1);
                v0.x += r0.x; v0.y += r0.y;
                v1.x += r1.x; v1.y += r1.y;
            }
            *(float2*)(Cout + o0) = v0;
            *(float2*)(Cout + o1) = v1;
        }
    }
}

// ---------------- flash attention, tensor-core tiles -------------------------
constexpr int QS_STRIDE = 68;
constexpr int VS_STRIDE = 72;
constexpr int ATTN_SMEM_WORDS = 3 * 64 * QS_STRIDE + 64 * VS_STRIDE + 192;
constexpr int ATTN_SMEM_BYTES = ATTN_SMEM_WORDS * 4;

__global__ __launch_bounds__(128) void attn_flash(
    const float* __restrict__ qkv, float* __restrict__ out)
{
    extern __shared__ float smem_f[];
    uint32_t* Qs = (uint32_t*)smem_f;
    uint32_t* Ks = Qs + 64 * QS_STRIDE;
    float*    Ss = (float*)(Ks + 64 * QS_STRIDE);
    uint32_t* SsU = (uint32_t*)Ss;
    uint32_t* Vs = (uint32_t*)(Ss + 64 * QS_STRIDE);
    float* row_m = (float*)(Vs + 64 * VS_STRIDE);
    float* row_l = row_m + 64;
    float* row_c = row_l + 64;

    int qt = blockIdx.x, head = blockIdx.y, b = blockIdx.z;
    int tid = threadIdx.x;
    int wid = tid >> 5, lane = tid & 31;
    int g = lane >> 2, tg = lane & 3;
    int wm = wid * 16;

    const float* qbase = qkv + (size_t)(b * cT + qt * 64) * cQKV + head * cHS;
    const float* kbase = qkv + (size_t)(b * cT) * cQKV + cC + head * cHS;
    const float* vbase = kbase + cC;

    {
        int r = tid >> 1, c0 = (tid & 1) * 32;
        const float* src = qbase + (size_t)r * cQKV + c0;
        uint32_t* dst = Qs + r * QS_STRIDE + c0;
        #pragma unroll
        for (int i = 0; i < 8; i++) {
            float4 v = *(const float4*)(src + i * 4);
            dst[i * 4 + 0] = f2tf(v.x * 0.125f);
            dst[i * 4 + 1] = f2tf(v.y * 0.125f);
            dst[i * 4 + 2] = f2tf(v.z * 0.125f);
            dst[i * 4 + 3] = f2tf(v.w * 0.125f);
        }
    }
    if (tid < 64) { row_m[tid] = -1e30f; row_l[tid] = 0.0f; }
    __syncthreads();

    uint32_t qf[8][4];
    #pragma unroll
    for (int kk = 0; kk < 8; kk++) {
        qf[kk][0] = Qs[(wm + g    ) * QS_STRIDE + kk * 8 + tg    ];
        qf[kk][1] = Qs[(wm + g + 8) * QS_STRIDE + kk * 8 + tg    ];
        qf[kk][2] = Qs[(wm + g    ) * QS_STRIDE + kk * 8 + tg + 4];
        qf[kk][3] = Qs[(wm + g + 8) * QS_STRIDE + kk * 8 + tg + 4];
    }

    float o[8][4];
    #pragma unroll
    for (int j = 0; j < 8; j++)
        #pragma unroll
        for (int r = 0; r < 4; r++) o[j][r] = 0.0f;

    int ntiles = qt + 1;
    for (int ti = 0; ti < ntiles; ti++) {
        int s0 = ti * 64;

        {
            int r = tid >> 1, c0 = (tid & 1) * 32;
            const float* ksrc = kbase + (size_t)(s0 + r) * cQKV + c0;
            const float* vsrc = vbase + (size_t)(s0 + r) * cQKV + c0;
            uint32_t* kdst = Ks + r * QS_STRIDE + c0;
            uint32_t* vdst = Vs + r * VS_STRIDE + c0;
            #pragma unroll
            for (int i = 0; i < 8; i++) {
                float4 kv = *(const float4*)(ksrc + i * 4);
                kdst[i * 4 + 0] = f2tf(kv.x);
                kdst[i * 4 + 1] = f2tf(kv.y);
                kdst[i * 4 + 2] = f2tf(kv.z);
                kdst[i * 4 + 3] = f2tf(kv.w);
                float4 vv = *(const float4*)(vsrc + i * 4);
                vdst[i * 4 + 0] = f2tf(vv.x);
                vdst[i * 4 + 1] = f2tf(vv.y);
                vdst[i * 4 + 2] = f2tf(vv.z);
                vdst[i * 4 + 3] = f2tf(vv.w);
            }
        }
        __syncthreads();

        #pragma unroll
        for (int jn = 0; jn < 8; jn++) {
            float sc[4] = {0.f, 0.f, 0.f, 0.f};
            #pragma unroll
            for (int kk = 0; kk < 8; kk++) {
                uint32_t bf[2];
                bf[0] = Ks[(jn * 8 + g) * QS_STRIDE + kk * 8 + tg    ];
                bf[1] = Ks[(jn * 8 + g) * QS_STRIDE + kk * 8 + tg + 4];
                mma_tf32(sc, qf[kk], bf);
            }
            Ss[(wm + g    ) * QS_STRIDE + jn * 8 + 2 * tg    ] = sc[0];
            Ss[(wm + g    ) * QS_STRIDE + jn * 8 + 2 * tg + 1] = sc[1];
            Ss[(wm + g + 8) * QS_STRIDE + jn * 8 + 2 * tg    ] = sc[2];
            Ss[(wm + g + 8) * QS_STRIDE + jn * 8 + 2 * tg + 1] = sc[3];
        }
        __syncwarp();

        {
            int rloc = wm + (lane >> 1);
            int half = lane & 1;
            float* srow = Ss + rloc * QS_STRIDE + half * 32;
            int ig = qt * 64 + rloc;
            int jbase = s0 + half * 32;
            bool diag = (ti == qt);

            float mx = -1e30f;
            if (diag) {
                #pragma unroll
                for (int c = 0; c < 32; c++) {
                    float v = (jbase + c <= ig) ? srow[c] : -1e30f;
                    srow[c] = v;
                    mx = fmaxf(mx, v);
                }
            } else {
                #pragma unroll
                for (int c = 0; c < 32; c++) mx = fmaxf(mx, srow[c]);
            }
            mx = fmaxf(mx, __shfl_xor_sync(0xffffffffu, mx, 1));

            float om = row_m[rloc];
            float nm = fmaxf(om, mx);
            float corr = __expf(om - nm);

            float se = 0.0f;
            uint32_t* prow = SsU + rloc * QS_STRIDE + half * 32;
            #pragma unroll
            for (int c = 0; c < 32; c++) {
                float e = __expf(srow[c] - nm);
                prow[c] = f2tf(e);
                se += e;
            }
            se += __shfl_xor_sync(0xffffffffu, se, 1);

            if (half == 0) {
                row_m[rloc] = nm;
                row_l[rloc] = row_l[rloc] * corr + se;
                row_c[rloc] = corr;
            }
        }
        __syncwarp();

        {
            float c0 = row_c[wm + g], c1 = row_c[wm + g + 8];
            #pragma unroll
            for (int j = 0; j < 8; j++) {
                o[j][0] *= c0; o[j][1] *= c0;
                o[j][2] *= c1; o[j][3] *= c1;
            }
        }
        #pragma unroll
        for (int kk = 0; kk < 8; kk++) {
            uint32_t pf[4];
            pf[0] = SsU[(wm + g    ) * QS_STRIDE + kk * 8 + tg    ];
            pf[1] = SsU[(wm + g + 8) * QS_STRIDE + kk * 8 + tg    ];
            pf[2] = SsU[(wm + g    ) * QS_STRIDE + kk * 8 + tg + 4];
            pf[3] = SsU[(wm + g + 8) * QS_STRIDE + kk * 8 + tg + 4];
            #pragma unroll
            for (int j = 0; j < 8; j++) {
                uint32_t bf[2];
                bf[0] = Vs[(kk * 8 + tg    ) * VS_STRIDE + j * 8 + g];
                bf[1] = Vs[(kk * 8 + tg + 4) * VS_STRIDE + j * 8 + g];
                mma_tf32(o[j], pf, bf);
            }
        }
        __syncthreads();
    }

    {
        float inv0 = 1.0f / row_l[wm + g];
        float inv1 = 1.0f / row_l[wm + g + 8];
        int r0 = b * cT + qt * 64 + wm + g;
        size_t base0 = (size_t)r0 * cC + head * cHS;
        size_t base1 = (size_t)(r0 + 8) * cC + head * cHS;
        #pragma unroll
        for (int j = 0; j < 8; j++) {
            int col = j * 8 + 2 * tg;
            float2 v0 = make_float2(o[j][0] * inv0, o[j][1] * inv0);
            float2 v1 = make_float2(o[j][2] * inv1, o[j][3] * inv1);
            *(float2*)(out + base0 + col) = v0;
            *(float2*)(out + base1 + col) = v1;
        }
    }
}

// ---------------- host orchestration ----------------------------------------
extern "C" void kernel_launch(void* const* d_in, const int* in_sizes, int n_in,
                              void* d_out, int out_size)
{
    const float* x   = (const float*)d_in[0];
    const float* Wq  = (const float*)d_in[1];
    const float* Wk  = (const float*)d_in[2];
    const float* Wv  = (const float*)d_in[3];
    const float* Wo  = (const float*)d_in[4];
    const float* bo  = (const float*)d_in[5];
    const float* W1  = (const float*)d_in[6];
    const float* b1  = (const float*)d_in[7];
    const float* W2  = (const float*)d_in[8];
    const float* b2  = (const float*)d_in[9];
    const float* g1  = (const float*)d_in[10];
    const float* be1 = (const float*)d_in[11];
    const float* g2  = (const float*)d_in[12];
    const float* be2 = (const float*)d_in[13];
    float* out = (float*)d_out;

    float *p_h, *p_wqkv, *p_qkv, *p_attn, *p_x1, *p_ff1;
    cudaGetSymbolAddress((void**)&p_h,    g_h);
    cudaGetSymbolAddress((void**)&p_wqkv, g_wqkv);
    cudaGetSymbolAddress((void**)&p_qkv,  g_qkv);
    cudaGetSymbolAddress((void**)&p_attn, g_attn);
    cudaGetSymbolAddress((void**)&p_x1,   g_x1);
    cudaGetSymbolAddress((void**)&p_ff1,  g_ff1);

    cudaFuncSetAttribute(attn_flash,
        cudaFuncAttributeMaxDynamicSharedMemorySize, ATTN_SMEM_BYTES);
    cudaFuncSetAttribute(gemm_tf32,
        cudaFuncAttributeMaxDynamicSharedMemorySize, GEMM_SMEM_BYTES);

    // 1. h = LN(x, g1, be1)
    ln_kernel<<<cBT, 128>>>(x, g1, be1, p_h);

    // 2. pack Wq|Wk|Wv -> Wqkv (C x 1152)
    pack_qkv_kernel<<<(cC * cQKV + 255) / 256, 256>>>(Wq, Wk, Wv, p_wqkv);

    // 3. qkv = h @ Wqkv   (BT x 1152)
    {
        dim3 grid(cQKV / 128, cBT / 128);
        gemm_tf32<<<grid, 256, GEMM_SMEM_BYTES>>>(p_h, p_wqkv, nullptr, nullptr, p_qkv, cBT, cQKV, cC, 0);
    }

    // 4. flash attention -> g_attn (BT x C)
    {
        dim3 grid(cT / 64, cH, cB);
        attn_flash<<<grid, 128, ATTN_SMEM_BYTES>>>(p_qkv, p_attn);
    }

    // 5. x1 = x + attn @ Wo + bo
    {
        dim3 grid(cC / 128, cBT / 128);
        gemm_tf32<<<grid, 256, GEMM_SMEM_BYTES>>>(p_attn, Wo, bo, x, p_x1, cBT, cC, cC, 0);
    }

    // 6. h2 = LN(x1, g2, be2)
    ln_kernel<<<cBT, 128>>>(p_x1, g2, be2, p_h);

    // 7. ff1 = relu(h2 @ W1 + b1)
    {
        dim3 grid(cDFF / 128, cBT / 128);
        gemm_tf32<<<grid, 256, GEMM_SMEM_BYTES>>>(p_h, W1, b1, nullptr, p_ff1, cBT, cDFF, cC, 1);
    }

    // 8. out = x1 + ff1 @ W2 + b2
    {
        dim3 grid(cC / 128, cBT / 128);
        gemm_tf32<<<grid, 256, GEMM_SMEM_BYTES>>>(p_ff1, W2, b2, p_x1, out, cBT, cC, cDFF, 0);
    }
}